// round 4
// baseline (speedup 1.0000x reference)
#include <cuda_runtime.h>
#include <cuda_bf16.h>

// Dense 3x3 conv, NCHW fp32, stride 1, pad 1, + bias.
// x: (32,128,56,56), w: (256,128,3,3), bias: (256) -> out: (32,256,56,56)
//
// R3: f32x2 pairs over ADJACENT OUTPUT CHANNELS.
//  - a-operand (w[oc],w[oc+1]) is a free register-pair reinterpret of LDS.128
//  - b-operand (xs,xs) replicated via one mov.b64 per use
//  - thread microtile: 8 oc x (2x4) px = 64 outputs, 0.33 smem-B/FLOP
//  - block: 64 oc x 8x28 spatial, 224 threads; 7x2 tiles cover 56x56 exactly
//    (zero waste, no store guards)

#define CK       8
#define TILE_OC  64
#define THREADS  224

typedef unsigned long long ull;

__device__ __forceinline__ ull pk2(float v) {
    ull r;
    asm("mov.b64 %0, {%1, %1};" : "=l"(r) : "f"(v));
    return r;
}
__device__ __forceinline__ void upk(float& lo, float& hi, ull v) {
    asm("mov.b64 {%0, %1}, %2;" : "=f"(lo), "=f"(hi) : "l"(v));
}
__device__ __forceinline__ void fma2(ull& d, ull a, ull b) {
    asm("fma.rn.f32x2 %0, %1, %2, %0;" : "+l"(d) : "l"(a), "l"(b));
}

__global__ __launch_bounds__(THREADS, 2)
void conv3x3_kernel(const float* __restrict__ x,
                    const float* __restrict__ wgt,
                    const float* __restrict__ bias,
                    float* __restrict__ out)
{
    // sW[r][oc]: r = c*9 + kh*3 + kw (72 rows), oc padded 64->68
    // (272B row stride: 16B-aligned ulonglong2/LDS.128 reads).
    __shared__ float sW[CK * 9][68];
    // Input tile: 8 rows + halo = 10, 28 cols + halo = 30, padded to 36
    // words (144B stride: 16B aligned, 4-bank skew per row -> the 4 row
    // groups of a warp hit distinct banks).
    __shared__ float sIn[CK][10][36];

    const int tid = threadIdx.x;
    const int pxi = tid % 28;
    const int ocg = tid / 28;          // 0..7
    const int ct  = pxi % 7;           // col-thread
    const int rt_ = pxi / 7;           // row-thread 0..3
    const int px0 = ct * 4;            // local output col base (0..24)
    const int y0  = rt_ * 2;           // local output row base (0,2,4,6)
    const int ocb = ocg * 8;

    const int brow = blockIdx.x >> 1;  // 0..6
    const int bcol = blockIdx.x & 1;   // 0..1
    const int o0   = blockIdx.y * TILE_OC;
    const int n    = blockIdx.z;

    const int h0 = brow * 8;
    const int w0 = bcol * 28;

    const float* xn = x + (size_t)n * 128 * 56 * 56;

    ull acc[4][2][4];                  // [oc-pair][oy][ox]
#pragma unroll
    for (int p = 0; p < 4; ++p)
#pragma unroll
        for (int oy = 0; oy < 2; ++oy)
#pragma unroll
            for (int ox = 0; ox < 4; ++ox) acc[p][oy][ox] = 0ull;

    for (int c0 = 0; c0 < 128; c0 += CK) {
        // ---- stage input tile (CK x 10 x 30, zero-padded halo) ----
        for (int idx = tid; idx < CK * 10 * 30; idx += THREADS) {
            int c   = idx / 300;
            int rem = idx - c * 300;
            int r   = rem / 30;
            int q   = rem - r * 30;
            int gh = h0 - 1 + r;
            int gw = w0 - 1 + q;
            float v = 0.0f;
            if ((unsigned)gh < 56u && (unsigned)gw < 56u)
                v = xn[((size_t)(c0 + c) * 56 + gh) * 56 + gw];
            sIn[c][r][q] = v;
        }
        // ---- stage weights (coalesced 72-float gmem runs per oc) ----
        for (int idx = tid; idx < CK * 9 * TILE_OC; idx += THREADS) {
            int oc = idx / (CK * 9);
            int r  = idx - oc * (CK * 9);
            sW[r][oc] = wgt[(size_t)(o0 + oc) * 1152 + c0 * 9 + r];
        }
        __syncthreads();

#pragma unroll
        for (int c = 0; c < CK; ++c) {
            // patch: rows y0..y0+3, cols px0..px0+5 (held in regs)
            float P[4][6];
#pragma unroll
            for (int d = 0; d < 4; ++d) {
                const float* row = &sIn[c][y0 + d][px0];
                const float4 a = *(const float4*)row;
                const float2 b = *(const float2*)(row + 4);
                P[d][0] = a.x; P[d][1] = a.y; P[d][2] = a.z;
                P[d][3] = a.w; P[d][4] = b.x; P[d][5] = b.y;
            }
#pragma unroll
            for (int kh = 0; kh < 3; ++kh) {
#pragma unroll
                for (int kw = 0; kw < 3; ++kw) {
                    const float* wr = &sW[c * 9 + kh * 3 + kw][ocb];
                    const ulonglong2 wA = *(const ulonglong2*)wr;       // (oc0,oc1)(oc2,oc3)
                    const ulonglong2 wB = *(const ulonglong2*)(wr + 4); // (oc4,oc5)(oc6,oc7)
#pragma unroll
                    for (int oy = 0; oy < 2; ++oy) {
#pragma unroll
                        for (int ox = 0; ox < 4; ++ox) {
                            const ull xx = pk2(P[oy + kh][ox + kw]);
                            fma2(acc[0][oy][ox], wA.x, xx);
                            fma2(acc[1][oy][ox], wA.y, xx);
                            fma2(acc[2][oy][ox], wB.x, xx);
                            fma2(acc[3][oy][ox], wB.y, xx);
                        }
                    }
                }
            }
        }
        __syncthreads();
    }

    // ---- epilogue: unpack per-oc, +bias, float4 stores (all in-bounds) ----
#pragma unroll
    for (int p = 0; p < 4; ++p) {
        const int olo = o0 + ocb + 2 * p;
        const float blo = __ldg(&bias[olo]);
        const float bhi = __ldg(&bias[olo + 1]);
        float* oplo = out + (((size_t)n * 256 + olo) * 56 + h0 + y0) * 56 + w0 + px0;
        float* ophi = oplo + (size_t)56 * 56;
#pragma unroll
        for (int oy = 0; oy < 2; ++oy) {
            float4 vlo, vhi;
            upk(vlo.x, vhi.x, acc[p][oy][0]);
            upk(vlo.y, vhi.y, acc[p][oy][1]);
            upk(vlo.z, vhi.z, acc[p][oy][2]);
            upk(vlo.w, vhi.w, acc[p][oy][3]);
            vlo.x += blo; vlo.y += blo; vlo.z += blo; vlo.w += blo;
            vhi.x += bhi; vhi.y += bhi; vhi.z += bhi; vhi.w += bhi;
            *(float4*)(oplo + oy * 56) = vlo;
            *(float4*)(ophi + oy * 56) = vhi;
        }
    }
}

extern "C" void kernel_launch(void* const* d_in, const int* in_sizes, int n_in,
                              void* d_out, int out_size)
{
    const float* x    = (const float*)d_in[0];
    const float* w    = (const float*)d_in[1];
    const float* bias = (const float*)d_in[2];
    float* out        = (float*)d_out;

    dim3 grid(14, 4, 32);   // (7 row-tiles * 2 col-tiles, oc-tiles, images)
    conv3x3_kernel<<<grid, THREADS>>>(x, w, bias, out);
}

// round 6
// speedup vs baseline: 1.6215x; 1.6215x over previous
#include <cuda_runtime.h>
#include <cuda_bf16.h>
#include <cstdint>

// 3x3 conv (NCHW fp32, pad 1, +bias) via mma.sync bf16 3-term split GEMM.
// x:(32,128,56,56) w:(256,128,3,3) b:(256) -> out:(32,256,56,56)
// D[128px,128oc] += sum over 9 taps x 3 terms x 128 ch of A·B^T
//   terms: (xh,wh), (xl,wh), (xh,wl)

#define ROWPAD 136          // bf16 elems per smem row (272 B)
#define ABUF   34816        // 128*136*2
#define SMEMSZ 139264       // 2*A + 2*B

__device__ __align__(16) __nv_bfloat16 g_wb[589824];     // [(ob*9+t)*2+hl][oc128][ch128]
__device__ __align__(16) __nv_bfloat16 g_xs[97517568];   // [hl][dw][n][c][62][64]

__device__ __forceinline__ uint32_t s2u(const void* p) {
    uint32_t a;
    asm("{ .reg .u64 t; cvta.to.shared.u64 t, %1; cvt.u32.u64 %0, t; }" : "=r"(a) : "l"(p));
    return a;
}
__device__ __forceinline__ void cpa16(uint32_t d, const void* s) {
    asm volatile("cp.async.cg.shared.global [%0], [%1], 16;" :: "r"(d), "l"(s) : "memory");
}
__device__ __forceinline__ void ldmA(uint32_t* r, uint32_t a) {   // x4 trans
    asm volatile("ldmatrix.sync.aligned.m8n8.x4.trans.shared.b16 {%0,%1,%2,%3}, [%4];"
        : "=r"(r[0]), "=r"(r[1]), "=r"(r[2]), "=r"(r[3]) : "r"(a));
}
__device__ __forceinline__ void ldmB(uint32_t* r, uint32_t a) {   // x4
    asm volatile("ldmatrix.sync.aligned.m8n8.x4.shared.b16 {%0,%1,%2,%3}, [%4];"
        : "=r"(r[0]), "=r"(r[1]), "=r"(r[2]), "=r"(r[3]) : "r"(a));
}
__device__ __forceinline__ void mmabf(float* d, const uint32_t* a, uint32_t b0, uint32_t b1) {
    asm volatile("mma.sync.aligned.m16n8k16.row.col.f32.bf16.bf16.f32 "
        "{%0,%1,%2,%3}, {%4,%5,%6,%7}, {%8,%9}, {%0,%1,%2,%3};"
        : "+f"(d[0]), "+f"(d[1]), "+f"(d[2]), "+f"(d[3])
        : "r"(a[0]), "r"(a[1]), "r"(a[2]), "r"(a[3]), "r"(b0), "r"(b1));
}

// ---- weight split: g_wb[(b*9+t)*2+hl][oc][ch] ----
__global__ void wsplit_kernel(const float* __restrict__ w) {
    int oc = blockIdx.x, ch = threadIdx.x;
    int b = oc >> 7, ocb = oc & 127;
    const float* src = w + ((size_t)oc * 128 + ch) * 9;
#pragma unroll
    for (int t = 0; t < 9; ++t) {
        float f = src[t];
        __nv_bfloat16 h = __float2bfloat16(f);
        __nv_bfloat16 l = __float2bfloat16(f - __bfloat162float(h));
        size_t base = (((size_t)(b * 9 + t) * 2) * 128 + ocb) * 128 + ch;
        g_wb[base] = h;
        g_wb[base + 16384] = l;
    }
}

// ---- x split + 3 dw-shifted padded copies ----
// g_xs[hl][dw][n][c][r][w'] = split of x[n][c][r-1][w'+dw-1] (0 if OOB).
// rows 58..61 never written (stay zero) — read only by out-of-range pixels.
__global__ void xsplit_kernel(const float* __restrict__ x) {
    long long i = (long long)blockIdx.x * 256 + threadIdx.x;   // < 45,613,056
    int wq = (int)(i & 63);
    long long q = i >> 6;
    int r  = (int)(q % 58);
    long long q2 = q / 58;
    int c  = (int)(q2 & 127);
    int q3 = (int)(q2 >> 7);
    int nn = q3 & 31;
    int dw = q3 >> 5;
    int row = r - 1, col = wq + dw - 1;
    float v = 0.0f;
    if ((unsigned)row < 56u && (unsigned)col < 56u)
        v = x[(((size_t)nn * 128 + c) * 56 + row) * 56 + col];
    __nv_bfloat16 h = __float2bfloat16(v);
    __nv_bfloat16 lo = __float2bfloat16(v - __bfloat162float(h));
    size_t base = (((size_t)dw * 32 + nn) * 128 + c) * 3968 + (size_t)r * 64 + wq;
    g_xs[base] = h;
    g_xs[(size_t)48758784 + base] = lo;
}

// ---- main GEMM kernel: 256 threads, warp tile 32x64 ----
__global__ __launch_bounds__(256, 1)
void conv_mma_kernel(const float* __restrict__ bias, float* __restrict__ out) {
    extern __shared__ __align__(16) char smem[];
    const uint32_t SB = s2u(smem);                 // A0,A1,B0,B1 each ABUF

    const int tid = threadIdx.x;
    const int p0  = blockIdx.x * 128;
    const int ob  = blockIdx.y;
    const int n   = blockIdx.z;

    // staging thread map: jj = 16B chunk (8 px or 8 ch), rows strided by 16
    const int jj = tid & 15;
    const int tr = tid >> 4;
    const int pchunk = p0 + 8 * jj;
    const int phc = pchunk / 56;
    const int pwc = pchunk - phc * 56;             // multiple of 8

    // mma thread map
    const int wid = tid >> 5, l = tid & 31;
    const int m0 = (wid & 3) * 32;
    const int n0 = (wid >> 2) * 64;
    const uint32_t aoff = (uint32_t)(((l & 7) + ((l >> 4) << 3)) * 272
                        + (m0 + (((l >> 3) & 1) << 3)) * 2);
    const uint32_t boff = (uint32_t)(((l & 7) + ((l >> 4) << 3)) * 272
                        + (((l >> 3) & 1) << 4) + n0 * 272);

    float acc[2][8][4];
#pragma unroll
    for (int a = 0; a < 2; ++a)
#pragma unroll
        for (int b = 0; b < 8; ++b)
#pragma unroll
            for (int c = 0; c < 4; ++c) acc[a][b][c] = 0.0f;

    auto issue = [&](int s) {
        const int tap = s / 3, term = s - 3 * tap;
        const int dh = tap / 3, dw = tap - 3 * dh;
        // A tile (always): hl = (term==1)
        {
            const int hl = (term == 1);
            const uint32_t ab = SB + (uint32_t)(s & 1) * ABUF;
            const __nv_bfloat16* src = g_xs
                + (((size_t)hl * 3 + dw) * 32 + n) * 128 * 3968
                + (size_t)(phc + dh) * 64 + pwc;
#pragma unroll
            for (int i = 0; i < 8; ++i) {
                int c = tr + 16 * i;
                cpa16(ab + (uint32_t)c * 272 + jj * 16, src + (size_t)c * 3968);
            }
        }
        // B tile (terms 0 and 2): hl = (term==2)
        if (term != 1) {
            const int hl = (term == 2);
            const uint32_t bb = SB + 2u * ABUF + (uint32_t)((tap * 2 + hl) & 1) * ABUF;
            const __nv_bfloat16* src = g_wb
                + ((size_t)(ob * 9 + tap) * 2 + hl) * 16384 + jj * 8;
#pragma unroll
            for (int i = 0; i < 8; ++i) {
                int oc = tr + 16 * i;
                cpa16(bb + (uint32_t)oc * 272 + jj * 16, src + (size_t)oc * 128);
            }
        }
        asm volatile("cp.async.commit_group;" ::: "memory");
    };

    issue(0);
    issue(1);

#pragma unroll 1
    for (int s = 0; s < 27; ++s) {
        if (s < 26) asm volatile("cp.async.wait_group 1;" ::: "memory");
        else        asm volatile("cp.async.wait_group 0;" ::: "memory");
        __syncthreads();

        const int tap = s / 3, term = s - 3 * tap;
        const uint32_t ab = SB + (uint32_t)(s & 1) * ABUF + aoff;
        const uint32_t bb = SB + 2u * ABUF
                          + (uint32_t)((tap * 2 + (term == 2)) & 1) * ABUF + boff;
#pragma unroll
        for (int kk = 0; kk < 8; ++kk) {
            uint32_t af[2][4];
            ldmA(af[0], ab + kk * 4352);
            ldmA(af[1], ab + kk * 4352 + 32);
#pragma unroll
            for (int np = 0; np < 4; ++np) {
                uint32_t bf[4];
                ldmB(bf, bb + np * (16 * 272) + kk * 32);
                mmabf(acc[0][2 * np],     af[0], bf[0], bf[1]);
                mmabf(acc[0][2 * np + 1], af[0], bf[2], bf[3]);
                mmabf(acc[1][2 * np],     af[1], bf[0], bf[1]);
                mmabf(acc[1][2 * np + 1], af[1], bf[2], bf[3]);
            }
        }
        __syncthreads();
        if (s + 2 < 27) issue(s + 2);
    }

    // ---- epilogue: +bias, guarded stores ----
    const int rbase = p0 + m0 + (l >> 2);
    const int cb = n0 + (l & 3) * 2;
#pragma unroll
    for (int mt = 0; mt < 2; ++mt)
#pragma unroll
        for (int h2 = 0; h2 < 2; ++h2) {
            const int p = rbase + mt * 16 + h2 * 8;
            if (p < 3136) {
#pragma unroll
                for (int nt = 0; nt < 8; ++nt) {
                    const int oc = ob * 128 + cb + nt * 8;
                    float* op = out + ((size_t)n * 256 + oc) * 3136 + p;
                    op[0]    = acc[mt][nt][h2 * 2]     + __ldg(&bias[oc]);
                    op[3136] = acc[mt][nt][h2 * 2 + 1] + __ldg(&bias[oc + 1]);
                }
            }
        }
}

extern "C" void kernel_launch(void* const* d_in, const int* in_sizes, int n_in,
                              void* d_out, int out_size)
{
    const float* x    = (const float*)d_in[0];
    const float* w    = (const float*)d_in[1];
    const float* bias = (const float*)d_in[2];
    float* out        = (float*)d_out;

    cudaFuncSetAttribute(conv_mma_kernel,
                         cudaFuncAttributeMaxDynamicSharedMemorySize, SMEMSZ);

    wsplit_kernel<<<256, 128>>>(w);
    xsplit_kernel<<<178176, 256>>>(x);
    dim3 grid(25, 2, 32);
    conv_mma_kernel<<<grid, 256, SMEMSZ>>>(bias, out);
}

// round 7
// speedup vs baseline: 2.1438x; 1.3221x over previous
#include <cuda_runtime.h>
#include <cuda_bf16.h>
#include <cstdint>

// 3x3 conv (NCHW fp32, pad 1, +bias) via mma.sync bf16 3-term split GEMM.
// R7: NHWC split-x (1 copy), term order (xh*wh, xh*wl, xl*wh),
//     3+3 ring buffers, ONE __syncthreads per stage, 18+18 stagings.

#define ABUF   34816                 // 128 rows * 272 B
#define SMEMSZ 208896                // 6 * ABUF
#define NSTR   445440                // 60*58*128
#define HLSTR  14254080              // 32*NSTR

__device__ __align__(16) __nv_bfloat16 g_wb[589824];     // [(ob*9+t)*2+hl][oc][ch]
__device__ __align__(16) __nv_bfloat16 g_xs[28508160];   // [hl][n][r60][w58][c128]

__device__ __forceinline__ uint32_t s2u(const void* p) {
    uint32_t a;
    asm("{ .reg .u64 t; cvta.to.shared.u64 t, %1; cvt.u32.u64 %0, t; }" : "=r"(a) : "l"(p));
    return a;
}
__device__ __forceinline__ void cpa16(uint32_t d, const void* s) {
    asm volatile("cp.async.cg.shared.global [%0], [%1], 16;" :: "r"(d), "l"(s) : "memory");
}
__device__ __forceinline__ void ldm4(uint32_t* r, uint32_t a) {
    asm volatile("ldmatrix.sync.aligned.m8n8.x4.shared.b16 {%0,%1,%2,%3}, [%4];"
        : "=r"(r[0]), "=r"(r[1]), "=r"(r[2]), "=r"(r[3]) : "r"(a));
}
__device__ __forceinline__ void mmabf(float* d, const uint32_t* a, uint32_t b0, uint32_t b1) {
    asm volatile("mma.sync.aligned.m16n8k16.row.col.f32.bf16.bf16.f32 "
        "{%0,%1,%2,%3}, {%4,%5,%6,%7}, {%8,%9}, {%0,%1,%2,%3};"
        : "+f"(d[0]), "+f"(d[1]), "+f"(d[2]), "+f"(d[3])
        : "r"(a[0]), "r"(a[1]), "r"(a[2]), "r"(a[3]), "r"(b0), "r"(b1));
}

// ---- weight split: g_wb[(b*9+t)*2+hl][oc][ch] ----
__global__ void wsplit_kernel(const float* __restrict__ w) {
    int oc = blockIdx.x, ch = threadIdx.x;
    int b = oc >> 7, ocb = oc & 127;
    const float* src = w + ((size_t)oc * 128 + ch) * 9;
#pragma unroll
    for (int t = 0; t < 9; ++t) {
        float f = src[t];
        __nv_bfloat16 h = __float2bfloat16(f);
        __nv_bfloat16 l = __float2bfloat16(f - __bfloat162float(h));
        size_t base = (((size_t)(b * 9 + t) * 2) * 128 + ocb) * 128 + ch;
        g_wb[base] = h;
        g_wb[base + 16384] = l;
    }
}

// ---- x split to NHWC with halo: g_xs[hl][n][r][w][c], r0..59, w0..57 ----
__global__ void xsplit_kernel(const float* __restrict__ x) {
    int i = blockIdx.x * 256 + threadIdx.x;       // < 890880
    int wq = i % 58;  i /= 58;
    int r  = i % 60;  i /= 60;
    int c16 = i & 7;
    int n   = i >> 3;
    const int row = r - 1, col = wq - 1;
    const bool v = (unsigned)row < 56u && (unsigned)col < 56u;
    const float* src = x + (((size_t)n * 128 + c16 * 16) * 56 + row) * 56 + col;
    __nv_bfloat16 hb[16], lb[16];
#pragma unroll
    for (int j = 0; j < 16; ++j) {
        float f = v ? __ldg(src + (size_t)j * 3136) : 0.0f;
        hb[j] = __float2bfloat16(f);
        lb[j] = __float2bfloat16(f - __bfloat162float(hb[j]));
    }
    size_t base = ((size_t)n * 3480 + r * 58 + wq) * 128 + c16 * 16;
    *(uint4*)(g_xs + base)             = *(uint4*)hb;
    *(uint4*)(g_xs + base + 8)         = *(uint4*)(hb + 8);
    *(uint4*)(g_xs + HLSTR + base)     = *(uint4*)lb;
    *(uint4*)(g_xs + HLSTR + base + 8) = *(uint4*)(lb + 8);
}

// stage ids: aId(s)=2*(s/3)+(s%3==2)  (xh,xh,xl per tap)
//            bId(s)=2*(s/3)+(s%3==1)  (wh,wl,wh per tap); bMax monotonic env.
__device__ __forceinline__ int aId(int s)  { return 2 * (s / 3) + ((s % 3) == 2); }
__device__ __forceinline__ int bId(int s)  { return 2 * (s / 3) + ((s % 3) == 1); }
__device__ __forceinline__ int bMax(int s) { return 2 * (s / 3) + ((s % 3) >= 1); }

__global__ __launch_bounds__(256, 1)
void conv_mma_kernel(const float* __restrict__ bias, float* __restrict__ out) {
    extern __shared__ __align__(16) char smem[];
    const uint32_t SB = s2u(smem);     // A rings: 0..2, B rings: 3..5 (x ABUF)

    const int tid = threadIdx.x;
    const int p0  = blockIdx.x * 128;
    const int ob  = blockIdx.y;
    const int n   = blockIdx.z;

    // staging map: jj = 16B ch-chunk, tr = row group
    const int jj = tid & 15;
    const int tr = tid >> 4;
    int q[8];                          // pixel offset in 58-wide padded frame
#pragma unroll
    for (int i = 0; i < 8; ++i) {
        int p = p0 + tr + 16 * i;
        q[i] = p + 2 * (p / 56);       // = (p/56)*58 + p%56
    }

    // mma map
    const int wid = tid >> 5, l = tid & 31;
    const int m0 = (wid & 3) * 32;
    const int n0 = (wid >> 2) * 64;
    const uint32_t aoff = (uint32_t)((m0 + (l & 15)) * 272 + (l >> 4) * 16);
    const uint32_t boff = (uint32_t)(((l & 7) + ((l >> 4) << 3)) * 272
                        + (((l >> 3) & 1) << 4) + n0 * 272);

    float acc[2][8][4];
#pragma unroll
    for (int a = 0; a < 2; ++a)
#pragma unroll
        for (int b = 0; b < 8; ++b)
#pragma unroll
            for (int c = 0; c < 4; ++c) acc[a][b][c] = 0.0f;

    auto stageA = [&](int id) {
        const int hl = id & 1, t = id >> 1;
        const uint32_t ab = SB + (uint32_t)(id % 3) * ABUF;
        const __nv_bfloat16* src = g_xs + (size_t)hl * HLSTR + (size_t)n * NSTR
                                 + (size_t)((t / 3) * 58 + (t % 3)) * 128 + jj * 8;
#pragma unroll
        for (int i = 0; i < 8; ++i)
            cpa16(ab + (uint32_t)(tr + 16 * i) * 272 + jj * 16,
                  src + (size_t)q[i] * 128);
    };
    auto stageB = [&](int id) {
        const int hl = id & 1, t = id >> 1;
        const uint32_t bb = SB + (3u + (uint32_t)(id % 3)) * ABUF;
        const __nv_bfloat16* src = g_wb + ((size_t)(ob * 9 + t) * 2 + hl) * 16384 + jj * 8;
#pragma unroll
        for (int i = 0; i < 8; ++i)
            cpa16(bb + (uint32_t)(tr + 16 * i) * 272 + jj * 16,
                  src + (size_t)(tr + 16 * i) * 128);
    };

    int na = 0, nb = 0;
    // prologue: data for stage 0
    while (na <= aId(0)) stageA(na++);
    while (nb <= bMax(0)) stageB(nb++);
    asm volatile("cp.async.commit_group;" ::: "memory");

#pragma unroll 1
    for (int s = 0; s < 27; ++s) {
        asm volatile("cp.async.wait_group 0;" ::: "memory");
        __syncthreads();
        if (s + 1 < 27) {
            while (na <= aId(s + 1)) stageA(na++);
            while (nb <= bMax(s + 1)) stageB(nb++);
        }
        asm volatile("cp.async.commit_group;" ::: "memory");

        const uint32_t ab = SB + (uint32_t)(aId(s) % 3) * ABUF + aoff;
        const uint32_t bb = SB + (3u + (uint32_t)(bId(s) % 3)) * ABUF + boff;
#pragma unroll
        for (int kk = 0; kk < 8; ++kk) {
            uint32_t af[2][4];
            ldm4(af[0], ab + kk * 32);
            ldm4(af[1], ab + kk * 32 + 16 * 272);
#pragma unroll
            for (int np = 0; np < 4; ++np) {
                uint32_t bf[4];
                ldm4(bf, bb + np * (16 * 272) + kk * 32);
                mmabf(acc[0][2 * np],     af[0], bf[0], bf[1]);
                mmabf(acc[0][2 * np + 1], af[0], bf[2], bf[3]);
                mmabf(acc[1][2 * np],     af[1], bf[0], bf[1]);
                mmabf(acc[1][2 * np + 1], af[1], bf[2], bf[3]);
            }
        }
    }

    // ---- epilogue: +bias, guarded stores ----
    const int rbase = p0 + m0 + (l >> 2);
    const int cb = n0 + (l & 3) * 2;
#pragma unroll
    for (int mt = 0; mt < 2; ++mt)
#pragma unroll
        for (int h2 = 0; h2 < 2; ++h2) {
            const int p = rbase + mt * 16 + h2 * 8;
            if (p < 3136) {
#pragma unroll
                for (int nt = 0; nt < 8; ++nt) {
                    const int oc = ob * 128 + cb + nt * 8;
                    float* op = out + ((size_t)n * 256 + oc) * 3136 + p;
                    op[0]    = acc[mt][nt][h2 * 2]     + __ldg(&bias[oc]);
                    op[3136] = acc[mt][nt][h2 * 2 + 1] + __ldg(&bias[oc + 1]);
                }
            }
        }
}

extern "C" void kernel_launch(void* const* d_in, const int* in_sizes, int n_in,
                              void* d_out, int out_size)
{
    const float* x    = (const float*)d_in[0];
    const float* w    = (const float*)d_in[1];
    const float* bias = (const float*)d_in[2];
    float* out        = (float*)d_out;

    cudaFuncSetAttribute(conv_mma_kernel,
                         cudaFuncAttributeMaxDynamicSharedMemorySize, SMEMSZ);

    wsplit_kernel<<<256, 128>>>(w);
    xsplit_kernel<<<3480, 256>>>(x);
    dim3 grid(25, 2, 32);
    conv_mma_kernel<<<grid, 256, SMEMSZ>>>(bias, out);
}

// round 8
// speedup vs baseline: 2.6343x; 1.2288x over previous
#include <cuda_runtime.h>
#include <cuda_bf16.h>
#include <cstdint>

// 3x3 conv (NCHW fp32, pad 1, +bias) via mma.sync bf16 3-term split GEMM.
// R8: CTA tile 64px x 128oc, 2 CTAs/SM (smem 112KB), XOR swizzle (no pad),
//     term order (xh*wh, xl*wh, xh*wl) -> A ring3(16K) + B ring2(32K).

#define ABUF   16384
#define BBUF   32768
#define SMEMSZ 114688                // 3*ABUF + 2*BBUF
#define NSTR   445440                // 60*58*128
#define HLSTR  14254080              // 32*NSTR

__device__ __align__(16) __nv_bfloat16 g_wb[589824];     // [(b*9+t)*2+hl][oc][ch]
__device__ __align__(16) __nv_bfloat16 g_xs[28508160];   // [hl][n][r60][w58][c128]

__device__ __forceinline__ uint32_t s2u(const void* p) {
    uint32_t a;
    asm("{ .reg .u64 t; cvta.to.shared.u64 t, %1; cvt.u32.u64 %0, t; }" : "=r"(a) : "l"(p));
    return a;
}
__device__ __forceinline__ void cpa16(uint32_t d, const void* s) {
    asm volatile("cp.async.cg.shared.global [%0], [%1], 16;" :: "r"(d), "l"(s) : "memory");
}
__device__ __forceinline__ void ldm4(uint32_t* r, uint32_t a) {
    asm volatile("ldmatrix.sync.aligned.m8n8.x4.shared.b16 {%0,%1,%2,%3}, [%4];"
        : "=r"(r[0]), "=r"(r[1]), "=r"(r[2]), "=r"(r[3]) : "r"(a));
}
__device__ __forceinline__ void mmabf(float* d, const uint32_t* a, uint32_t b0, uint32_t b1) {
    asm volatile("mma.sync.aligned.m16n8k16.row.col.f32.bf16.bf16.f32 "
        "{%0,%1,%2,%3}, {%4,%5,%6,%7}, {%8,%9}, {%0,%1,%2,%3};"
        : "+f"(d[0]), "+f"(d[1]), "+f"(d[2]), "+f"(d[3])
        : "r"(a[0]), "r"(a[1]), "r"(a[2]), "r"(a[3]), "r"(b0), "r"(b1));
}

// ---- merged prep: blocks <3480 split x (NHWC+halo), blocks >=3480 split w ----
__global__ void prep_kernel(const float* __restrict__ x, const float* __restrict__ w) {
    if (blockIdx.x < 3480) {
        int i = blockIdx.x * 256 + threadIdx.x;       // < 890880
        int wq = i % 58;  i /= 58;
        int r  = i % 60;  i /= 60;
        int c16 = i & 7;
        int n   = i >> 3;
        const int row = r - 1, col = wq - 1;
        const bool v = (unsigned)row < 56u && (unsigned)col < 56u;
        const float* src = x + (((size_t)n * 128 + c16 * 16) * 56 + row) * 56 + col;
        __nv_bfloat16 hb[16], lb[16];
#pragma unroll
        for (int j = 0; j < 16; ++j) {
            float f = v ? __ldg(src + (size_t)j * 3136) : 0.0f;
            hb[j] = __float2bfloat16(f);
            lb[j] = __float2bfloat16(f - __bfloat162float(hb[j]));
        }
        size_t base = ((size_t)n * 3480 + r * 58 + wq) * 128 + c16 * 16;
        *(uint4*)(g_xs + base)             = *(uint4*)hb;
        *(uint4*)(g_xs + base + 8)         = *(uint4*)(hb + 8);
        *(uint4*)(g_xs + HLSTR + base)     = *(uint4*)lb;
        *(uint4*)(g_xs + HLSTR + base + 8) = *(uint4*)(lb + 8);
    } else if (threadIdx.x < 128) {
        int oc = blockIdx.x - 3480, ch = threadIdx.x;
        int b = oc >> 7, ocb = oc & 127;
        const float* src = w + ((size_t)oc * 128 + ch) * 9;
#pragma unroll
        for (int t = 0; t < 9; ++t) {
            float f = src[t];
            __nv_bfloat16 h = __float2bfloat16(f);
            __nv_bfloat16 l = __float2bfloat16(f - __bfloat162float(h));
            size_t base = (((size_t)(b * 9 + t) * 2) * 128 + ocb) * 128 + ch;
            g_wb[base] = h;
            g_wb[base + 16384] = l;
        }
    }
}

// stage s: term pos = s%3 -> (xh*wh, xl*wh, xh*wl)
__device__ __forceinline__ int aId(int s)  { return 2 * (s / 3) + ((s % 3) == 1); }
__device__ __forceinline__ int bId(int s)  { return 2 * (s / 3) + ((s % 3) == 2); }
__device__ __forceinline__ int aMax(int s) { return aId(s); }   // monotone envelope:
__device__ __forceinline__ int bMax(int s) { return bId(s); }   // both nondecreasing? a: 2t,2t+1,2t
// NOTE: aId is not monotone within a tap (2t,2t+1,2t); the na counter uses the
// running max, so define explicit envelopes:
__device__ __forceinline__ int aEnv(int s) { return 2 * (s / 3) + ((s % 3) >= 1); }
__device__ __forceinline__ int bEnv(int s) { return 2 * (s / 3) + ((s % 3) == 2); }

__global__ __launch_bounds__(256, 2)
void conv_mma_kernel(const float* __restrict__ bias, float* __restrict__ out) {
    extern __shared__ __align__(16) char smem[];
    const uint32_t SB = s2u(smem);       // A rings 0..2 (ABUF), B rings at +3*ABUF

    const int tid = threadIdx.x;
    const int p0  = blockIdx.x * 64;
    const int ob  = blockIdx.y;
    const int n   = blockIdx.z;

    // staging map: jj = 16B ch-chunk (0..15), tr = row group (0..15)
    const int jj = tid & 15;
    const int tr = tid >> 4;
    int q[4];
#pragma unroll
    for (int i = 0; i < 4; ++i) {
        int p = p0 + tr + 16 * i;
        q[i] = p + 2 * (p / 56);         // offset in 58-wide padded frame
    }

    // mma map: 8 warps = 2(M) x 4(N); warp tile 32x32
    const int wid = tid >> 5, l = tid & 31;
    const int m0 = (wid & 1) * 32;
    const int n0 = (wid >> 1) * 32;
    const int rA0 = m0 + (l & 15);       // A rows (x4 frag), +16 for upper half
    const int ahx = rA0 & 7;             // swizzle xor for A rows (same for +16)
    const int ahi = l >> 4;              // A k-half select
    const int rBb = (l & 7) + ((l >> 4) << 3);
    const int bhalf = (l >> 3) & 1;
    const int bhx = l & 7;               // swizzle xor for B rows

    float acc[2][4][4];
#pragma unroll
    for (int a = 0; a < 2; ++a)
#pragma unroll
        for (int b = 0; b < 4; ++b)
#pragma unroll
            for (int c = 0; c < 4; ++c) acc[a][b][c] = 0.0f;

    auto stageA = [&](int id) {
        const int hl = id & 1, t = id >> 1;
        const uint32_t ab = SB + (uint32_t)(id % 3) * ABUF;
        const __nv_bfloat16* src = g_xs + (size_t)hl * HLSTR + (size_t)n * NSTR
                                 + (size_t)((t / 3) * 58 + (t % 3)) * 128 + jj * 8;
#pragma unroll
        for (int i = 0; i < 4; ++i) {
            int r = tr + 16 * i;
            cpa16(ab + (uint32_t)r * 256 + (uint32_t)((jj ^ (r & 7)) << 4),
                  src + (size_t)q[i] * 128);
        }
    };
    auto stageB = [&](int id) {
        const int hl = id & 1, t = id >> 1;
        const uint32_t bb = SB + 3u * ABUF + (uint32_t)(id & 1 ? (id % 2) : (id % 2)) * BBUF;
        const uint32_t bb2 = SB + 3u * ABUF + (uint32_t)(id % 2) * BBUF;
        (void)bb;
        const __nv_bfloat16* src = g_wb + ((size_t)(ob * 9 + t) * 2 + hl) * 16384 + jj * 8;
#pragma unroll
        for (int i = 0; i < 8; ++i) {
            int r = tr + 16 * i;
            cpa16(bb2 + (uint32_t)r * 256 + (uint32_t)((jj ^ (r & 7)) << 4),
                  src + (size_t)r * 128);
        }
    };

    int na = 0, nb = 0;
    while (na <= aEnv(0)) stageA(na++);
    while (nb <= bEnv(0)) stageB(nb++);
    asm volatile("cp.async.commit_group;" ::: "memory");

#pragma unroll 1
    for (int s = 0; s < 27; ++s) {
        asm volatile("cp.async.wait_group 0;" ::: "memory");
        __syncthreads();
        if (s + 1 < 27) {
            while (na <= aEnv(s + 1)) stageA(na++);
            while (nb <= bEnv(s + 1)) stageB(nb++);
        }
        asm volatile("cp.async.commit_group;" ::: "memory");

        const uint32_t ab = SB + (uint32_t)(aId(s) % 3) * ABUF;
        const uint32_t bb = SB + 3u * ABUF + (uint32_t)(bId(s) % 2) * BBUF;
#pragma unroll
        for (int kk = 0; kk < 8; ++kk) {
            uint32_t af[2][4];
            const uint32_t ac = (uint32_t)(((kk * 2 + ahi) ^ ahx) << 4);
            ldm4(af[0], ab + (uint32_t)rA0 * 256 + ac);
            ldm4(af[1], ab + (uint32_t)rA0 * 256 + 4096 + ac);
            const uint32_t bc = (uint32_t)(((kk * 2 + bhalf) ^ bhx) << 4);
#pragma unroll
            for (int np = 0; np < 2; ++np) {
                uint32_t bf[4];
                ldm4(bf, bb + (uint32_t)(n0 + np * 16 + rBb) * 256 + bc);
                mmabf(acc[0][2 * np],     af[0], bf[0], bf[1]);
                mmabf(acc[0][2 * np + 1], af[0], bf[2], bf[3]);
                mmabf(acc[1][2 * np],     af[1], bf[0], bf[1]);
                mmabf(acc[1][2 * np + 1], af[1], bf[2], bf[3]);
            }
        }
    }

    // ---- epilogue: +bias, stores (exact cover, no guards) ----
    const int rbase = p0 + m0 + (l >> 2);
    const int cb = n0 + (l & 3) * 2;
#pragma unroll
    for (int mt = 0; mt < 2; ++mt)
#pragma unroll
        for (int h2 = 0; h2 < 2; ++h2) {
            const int p = rbase + mt * 16 + h2 * 8;
#pragma unroll
            for (int nt = 0; nt < 4; ++nt) {
                const int oc = ob * 128 + cb + nt * 8;
                float* op = out + ((size_t)n * 256 + oc) * 3136 + p;
                op[0]    = acc[mt][nt][h2 * 2]     + __ldg(&bias[oc]);
                op[3136] = acc[mt][nt][h2 * 2 + 1] + __ldg(&bias[oc + 1]);
            }
        }
}

extern "C" void kernel_launch(void* const* d_in, const int* in_sizes, int n_in,
                              void* d_out, int out_size)
{
    const float* x    = (const float*)d_in[0];
    const float* w    = (const float*)d_in[1];
    const float* bias = (const float*)d_in[2];
    float* out        = (float*)d_out;

    cudaFuncSetAttribute(conv_mma_kernel,
                         cudaFuncAttributeMaxDynamicSharedMemorySize, SMEMSZ);

    prep_kernel<<<3736, 256>>>(x, w);
    dim3 grid(49, 2, 32);                // 49 px-blocks of 64, 2 oc-blocks, 32 n
    conv_mma_kernel<<<grid, 256, SMEMSZ>>>(bias, out);
}